// round 15
// baseline (speedup 1.0000x reference)
#include <cuda_runtime.h>
#include <cuda_fp16.h>
#include <math.h>
#include <stdint.h>

#define BATCH   4
#define LSEQ    8192
#define DMODEL  1024
#define NHEADS  16
#define DHEAD   64
#define MROWS   (BATCH * LSEQ)          // 32768
#define EPSV    1e-6f

// GEMM tiling: CTA 128x128, 8 warps (2x4), warp 64x32, k-stage 32 (fp16).
#define BM      128
#define BN      128
#define KSTG    32
#define NSTG    (DMODEL / KSTG)         // 32
#define RSB     80
#define BOFF    (BM * RSB)
#define STG_B   ((BM + BN) * RSB)       // 20480
#define GSMEM   (4 * STG_B)             // 81920

// kv_reduce (tensor-core) tiling
#define KVCH    16
#define KVL     (LSEQ / KVCH)           // 512
#define KROW    144
#define KBUF    (64 * KROW)             // 9216
#define KV_SMEM 66560
#define ONES16  0x3C003C00u

// ---------------- scratch (device globals; no allocations allowed) ----------
static __device__ __half g_xh  [(size_t)MROWS * DMODEL];
static __device__ __half g_Wth [(size_t)4 * DMODEL * DMODEL];           // [N,K] fp16 W
static __device__ __half g_Qfh [(size_t)MROWS * DMODEL];
static __device__ __half g_Kfh [(size_t)MROWS * DMODEL];
static __device__ __half g_Vh  [(size_t)MROWS * DMODEL];
static __device__ __half g_ath [(size_t)MROWS * DMODEL];
static __device__ float  g_KvP [(size_t)KVCH * BATCH * NHEADS * DHEAD * DHEAD];
static __device__ float  g_K1P [(size_t)KVCH * BATCH * NHEADS * DHEAD];
static __device__ __half g_Kvh [(size_t)BATCH * NHEADS * DHEAD * DHEAD];  // [bh][n][k] fp16
static __device__ __half g_K1h [(size_t)BATCH * NHEADS * DHEAD];

// ---------------- helpers ----------------------------------------------------
__device__ __forceinline__ uint32_t smem_u32(const void* p) {
    uint32_t a;
    asm("{ .reg .u64 t; cvta.to.shared.u64 t, %1; cvt.u32.u64 %0, t; }" : "=r"(a) : "l"(p));
    return a;
}
__device__ __forceinline__ void cp_async16(uint32_t saddr, const void* gptr) {
    asm volatile("cp.async.cg.shared.global [%0], [%1], 16;" :: "r"(saddr), "l"(gptr));
}
__device__ __forceinline__ void cp_commit() { asm volatile("cp.async.commit_group;"); }
template <int N> __device__ __forceinline__ void cp_wait() {
    asm volatile("cp.async.wait_group %0;" :: "n"(N));
}
__device__ __forceinline__ void mma_f16(float c[4],
                                        uint32_t a0, uint32_t a1, uint32_t a2, uint32_t a3,
                                        uint32_t b0, uint32_t b1)
{
    asm volatile("mma.sync.aligned.m16n8k16.row.col.f32.f16.f16.f32 "
                 "{%0,%1,%2,%3}, {%4,%5,%6,%7}, {%8,%9}, {%0,%1,%2,%3};"
                 : "+f"(c[0]), "+f"(c[1]), "+f"(c[2]), "+f"(c[3])
                 : "r"(a0), "r"(a1), "r"(a2), "r"(a3), "r"(b0), "r"(b1));
}
__device__ __forceinline__ void ldsm_x4(uint32_t& r0, uint32_t& r1, uint32_t& r2, uint32_t& r3,
                                        uint32_t addr)
{
    asm volatile("ldmatrix.sync.aligned.m8n8.x4.shared.b16 {%0,%1,%2,%3}, [%4];"
                 : "=r"(r0), "=r"(r1), "=r"(r2), "=r"(r3) : "r"(addr));
}
__device__ __forceinline__ void ldsm_x4t(uint32_t& r0, uint32_t& r1, uint32_t& r2, uint32_t& r3,
                                         uint32_t addr)
{
    asm volatile("ldmatrix.sync.aligned.m8n8.x4.trans.shared.b16 {%0,%1,%2,%3}, [%4];"
                 : "=r"(r0), "=r"(r1), "=r"(r2), "=r"(r3) : "r"(addr));
}

// ---------------- pre-passes --------------------------------------------------
__global__ void to_half_kernel(const float* __restrict__ in, __half* __restrict__ out, int n4)
{
    int i = blockIdx.x * blockDim.x + threadIdx.x;
    if (i < n4) {
        float4 v = ((const float4*)in)[i];
        __half2 h0 = __floats2half2_rn(v.x, v.y);
        __half2 h1 = __floats2half2_rn(v.z, v.w);
        ((uint2*)out)[i] = make_uint2(*(uint32_t*)&h0, *(uint32_t*)&h1);
    }
}

__global__ void transpose_all_kernel(const float* __restrict__ Wq, const float* __restrict__ Wk,
                                     const float* __restrict__ Wv, const float* __restrict__ Wo,
                                     __half* __restrict__ dst)
{
    __shared__ float t[32][33];
    const float* src = (blockIdx.z == 0) ? Wq : (blockIdx.z == 1) ? Wk
                     : (blockIdx.z == 2) ? Wv : Wo;
    __half* d = dst + (size_t)blockIdx.z * DMODEL * DMODEL;
    const int bx = blockIdx.x * 32, by = blockIdx.y * 32;
    const int tx = threadIdx.x, ty = threadIdx.y;
    #pragma unroll
    for (int j = ty; j < 32; j += 8)
        t[j][tx] = src[(size_t)(by + j) * DMODEL + bx + tx];
    __syncthreads();
    #pragma unroll
    for (int j = ty; j < 32; j += 8)
        d[(size_t)(bx + j) * DMODEL + by + tx] = __float2half_rn(t[tx][j]);
}

// ---------------- fp16 mma.sync GEMM with ldmatrix ---------------------------
template <int MODE>
__global__ __launch_bounds__(256, 2)
void gemm_f16_kernel(const __half* __restrict__ A, const __half* __restrict__ Bt,
                     float* __restrict__ Cf)
{
    extern __shared__ __align__(16) char smc[];
    const uint32_t sb = smem_u32(smc);

    const int tid  = threadIdx.x;
    const int lane = tid & 31;
    const int wid  = tid >> 5;
    const int bm   = blockIdx.y * BM;
    const int bn   = blockIdx.x * BN;
    const int wm   = (wid >> 2) * 64;
    const int wn   = (wid & 3) * 32;

    const int srow = tid >> 2;
    const int sch  = tid & 3;

    auto load_stage = [&](int s) {
        const uint32_t st = sb + (uint32_t)(s & 3) * STG_B;
        const int k0 = s * KSTG + sch * 8;
        cp_async16(st + (uint32_t)srow * RSB + sch * 16,
                   A + (size_t)(bm + srow) * DMODEL + k0);
        cp_async16(st + (uint32_t)(srow + 64) * RSB + sch * 16,
                   A + (size_t)(bm + srow + 64) * DMODEL + k0);
        cp_async16(st + BOFF + (uint32_t)srow * RSB + sch * 16,
                   Bt + (size_t)(bn + srow) * DMODEL + k0);
        cp_async16(st + BOFF + (uint32_t)(srow + 64) * RSB + sch * 16,
                   Bt + (size_t)(bn + srow + 64) * DMODEL + k0);
    };

    const uint32_t a_off = (uint32_t)(wm + ((lane >> 3) & 1) * 8 + (lane & 7)) * RSB
                         + (uint32_t)(lane >> 4) * 16;
    const uint32_t b_off = BOFF + (uint32_t)(wn + (lane >> 4) * 8 + (lane & 7)) * RSB
                         + (uint32_t)((lane >> 3) & 1) * 16;

    float acc[4][4][4];
    #pragma unroll
    for (int mt = 0; mt < 4; mt++)
        #pragma unroll
        for (int nt = 0; nt < 4; nt++)
            #pragma unroll
            for (int i = 0; i < 4; i++) acc[mt][nt][i] = 0.f;

    load_stage(0); cp_commit();
    load_stage(1); cp_commit();
    load_stage(2); cp_commit();

    #pragma unroll 1
    for (int c = 0; c < NSTG; c++) {
        cp_wait<2>();
        __syncthreads();

        if (c + 3 < NSTG) load_stage(c + 3);
        cp_commit();

        const uint32_t st = sb + (uint32_t)(c & 3) * STG_B;
        #pragma unroll
        for (int ks = 0; ks < 2; ks++) {
            const uint32_t ko = (uint32_t)ks * 32;
            uint32_t bfr[4][2];
            ldsm_x4(bfr[0][0], bfr[0][1], bfr[1][0], bfr[1][1], st + b_off + ko);
            ldsm_x4(bfr[2][0], bfr[2][1], bfr[3][0], bfr[3][1], st + b_off + 16 * RSB + ko);
            #pragma unroll
            for (int mt = 0; mt < 4; mt++) {
                uint32_t a0, a1, a2, a3;
                ldsm_x4(a0, a1, a2, a3, st + a_off + mt * (16 * RSB) + ko);
                #pragma unroll
                for (int nt = 0; nt < 4; nt++)
                    mma_f16(acc[mt][nt], a0, a1, a2, a3, bfr[nt][0], bfr[nt][1]);
            }
        }
    }

    const int lr = lane >> 2;
    const int lc = lane & 3;

    if (MODE == 0) {
        #pragma unroll
        for (int mt = 0; mt < 4; mt++)
            #pragma unroll
            for (int nt = 0; nt < 4; nt++) {
                const int row0 = bm + wm + mt * 16 + lr;
                const int col  = bn + wn + nt * 8 + lc * 2;
                *(float2*)(Cf + (size_t)row0 * DMODEL + col) =
                    make_float2(acc[mt][nt][0], acc[mt][nt][1]);
                *(float2*)(Cf + (size_t)(row0 + 8) * DMODEL + col) =
                    make_float2(acc[mt][nt][2], acc[mt][nt][3]);
            }
    } else {
        const int seg = bn >> 10;             // 0=Q, 1=K, 2=V
        const int bnl = bn & 1023;
        __half* outp = (seg == 0) ? g_Qfh : (seg == 1) ? g_Kfh : g_Vh;
        const bool phi = (seg < 2);
        #pragma unroll
        for (int mt = 0; mt < 4; mt++)
            #pragma unroll
            for (int nt = 0; nt < 4; nt++) {
                const int row0 = bm + wm + mt * 16 + lr;
                const int col  = bnl + wn + nt * 8 + lc * 2;
                float v[4];
                #pragma unroll
                for (int i = 0; i < 4; i++) {
                    float t = acc[mt][nt][i];
                    if (phi) t = (t > 0.f) ? (t + 1.f) : __expf(t);
                    v[i] = t;
                }
                __half2 h0 = __floats2half2_rn(v[0], v[1]);
                __half2 h1 = __floats2half2_rn(v[2], v[3]);
                *(uint32_t*)(outp + (size_t)row0 * DMODEL + col)       = *(uint32_t*)&h0;
                *(uint32_t*)(outp + (size_t)(row0 + 8) * DMODEL + col) = *(uint32_t*)&h1;
            }
    }
}

// ---------------- Kv / K1 reduction on tensor cores ---------------------------
__global__ __launch_bounds__(256, 2)
void kv_reduce_mma_kernel()
{
    extern __shared__ __align__(16) char km[];
    const uint32_t sb = smem_u32(km);
    const int tid  = threadIdx.x;
    const int lane = tid & 31;
    const int wid  = tid >> 5;
    const int chunk = blockIdx.x;
    const int h     = blockIdx.y;
    const int b     = blockIdx.z;
    const int bh    = b * NHEADS + h;
    const int mg = wid & 1;
    const int lg = wid >> 1;
    const int lb = lg * 16;

    auto load_sub = [&](int sub, int buf) {
        const uint32_t base = sb + (uint32_t)buf * (2 * KBUF);
        const int l0 = chunk * KVL + sub * 64;
        #pragma unroll
        for (int i = 0; i < 2; i++) {
            const int idx = tid + i * 256;
            const int row = idx >> 3, ch = idx & 7;
            size_t g = ((size_t)b * LSEQ + l0 + row) * DMODEL + h * DHEAD + ch * 8;
            cp_async16(base + (uint32_t)row * KROW + ch * 16,        g_Kfh + g);
            cp_async16(base + KBUF + (uint32_t)row * KROW + ch * 16, g_Vh + g);
        }
    };

    const uint32_t a_lane = (uint32_t)(lb + (lane >> 4) * 8 + (lane & 7)) * KROW
                          + (uint32_t)((lane >> 3) & 1) * 16;
    const uint32_t b_lane = KBUF + (uint32_t)(lb + ((lane >> 3) & 1) * 8 + (lane & 7)) * KROW
                          + (uint32_t)(lane >> 4) * 16;

    float accK[2][8][4];
    float accS[2][4];
    #pragma unroll
    for (int mt = 0; mt < 2; mt++) {
        #pragma unroll
        for (int nt = 0; nt < 8; nt++)
            #pragma unroll
            for (int i = 0; i < 4; i++) accK[mt][nt][i] = 0.f;
        #pragma unroll
        for (int i = 0; i < 4; i++) accS[mt][i] = 0.f;
    }

    load_sub(0, 0); cp_commit();

    #pragma unroll 1
    for (int sub = 0; sub < 8; sub++) {
        if (sub < 7) { load_sub(sub + 1, (sub + 1) & 1); cp_commit(); cp_wait<1>(); }
        else         { cp_wait<0>(); }
        __syncthreads();

        const uint32_t base = sb + (uint32_t)(sub & 1) * (2 * KBUF);
        uint32_t bfr[8][2];
        #pragma unroll
        for (int p = 0; p < 4; p++)
            ldsm_x4t(bfr[2*p][0], bfr[2*p][1], bfr[2*p+1][0], bfr[2*p+1][1],
                     base + b_lane + (uint32_t)p * 32);
        #pragma unroll
        for (int mt = 0; mt < 2; mt++) {
            uint32_t a0, a1, a2, a3;
            ldsm_x4t(a0, a1, a2, a3, base + a_lane + (uint32_t)(mg * 32 + mt * 16) * 2);
            #pragma unroll
            for (int nt = 0; nt < 8; nt++)
                mma_f16(accK[mt][nt], a0, a1, a2, a3, bfr[nt][0], bfr[nt][1]);
            mma_f16(accS[mt], a0, a1, a2, a3, ONES16, ONES16);
        }
        __syncthreads();
    }

    float* red   = (float*)km;             // [4][64][64]
    float* redk1 = (float*)(km + 65536);   // [4][64]
    const int lr = lane >> 2;
    const int lc = lane & 3;
    #pragma unroll
    for (int mt = 0; mt < 2; mt++) {
        const int m = mg * 32 + mt * 16 + lr;
        #pragma unroll
        for (int nt = 0; nt < 8; nt++) {
            const int n = nt * 8 + lc * 2;
            *(float2*)&red[((lg * 64 + m) * 64) + n]     = make_float2(accK[mt][nt][0], accK[mt][nt][1]);
            *(float2*)&red[((lg * 64 + m + 8) * 64) + n] = make_float2(accK[mt][nt][2], accK[mt][nt][3]);
        }
        if (lc == 0) {
            redk1[lg * 64 + m]     = accS[mt][0];
            redk1[lg * 64 + m + 8] = accS[mt][2];
        }
    }
    __syncthreads();

    for (int i = tid; i < 4096; i += 256) {
        float s = red[i] + red[4096 + i] + red[8192 + i] + red[12288 + i];
        g_KvP[((size_t)chunk * (BATCH * NHEADS) + bh) * 4096 + i] = s;
    }
    if (tid < 64) {
        float s = redk1[tid] + redk1[64 + tid] + redk1[128 + tid] + redk1[192 + tid];
        g_K1P[((size_t)chunk * (BATCH * NHEADS) + bh) * 64 + tid] = s;
    }
}

// ---------------- finalize: sum partials, emit fp16 Kv^T [n,k] and K1 --------
__global__ void kv_finalize_kernel()
{
    const int i = blockIdx.x * blockDim.x + threadIdx.x;
    const int KV_ELEMS = BATCH * NHEADS * DHEAD * DHEAD;
    const int K1_ELEMS = BATCH * NHEADS * DHEAD;
    if (i < KV_ELEMS) {
        float s = 0.f;
        #pragma unroll
        for (int c = 0; c < KVCH; c++) s += g_KvP[(size_t)c * KV_ELEMS + i];
        // i = bh*4096 + k*64 + n  -> store transposed [bh][n][k]
        const int bh = i >> 12, rem = i & 4095, k = rem >> 6, n = rem & 63;
        g_Kvh[((size_t)bh << 12) + (n << 6) + k] = __float2half_rn(s);
    }
    if (i < K1_ELEMS) {
        float s = 0.f;
        #pragma unroll
        for (int c = 0; c < KVCH; c++) s += g_K1P[(size_t)c * K1_ELEMS + i];
        g_K1h[i] = __float2half_rn(s);
    }
}

// ---------------- apply (tensor cores): out = (Qf@Kv) / (Qf@K1 + eps) --------
// grid (L/128, H, B); 8 warps, each one m16 row-tile. A = Qf (non-trans ldsm),
// B = Kvh[n,k] (non-trans ldsm), den via extra MMA against K1-broadcast B frag.
#define AROW 144
__global__ __launch_bounds__(256, 2)
void attn_apply_mma_kernel()
{
    __shared__ __align__(16) char sm[128 * AROW + 64 * AROW + 128];
    const uint32_t sb = smem_u32(sm);
    const uint32_t KVOFF = 128 * AROW;
    const uint32_t K1OFF = KVOFF + 64 * AROW;

    const int tid  = threadIdx.x;
    const int lane = tid & 31;
    const int w    = tid >> 5;
    const int lt = blockIdx.x, h = blockIdx.y, b = blockIdx.z;
    const int bh = b * NHEADS + h;

    // load Qf tile [128,64] + Kvh [64,64] + K1h [64]
    for (int i = tid; i < 1024; i += 256) {
        const int r = i >> 3, ch = i & 7;
        cp_async16(sb + (uint32_t)r * AROW + ch * 16,
                   g_Qfh + ((size_t)b * LSEQ + lt * 128 + r) * DMODEL + h * DHEAD + ch * 8);
    }
    for (int i = tid; i < 512; i += 256) {
        const int r = i >> 3, ch = i & 7;
        cp_async16(sb + KVOFF + (uint32_t)r * AROW + ch * 16,
                   g_Kvh + ((size_t)bh << 12) + r * 64 + ch * 8);
    }
    if (tid < 8)
        cp_async16(sb + K1OFF + tid * 16, g_K1h + bh * 64 + tid * 8);
    cp_commit(); cp_wait<0>();
    __syncthreads();

    const __half2* sK1 = (const __half2*)(sm + K1OFF);
    const int lc = lane & 3;

    float accK[8][4];
    float accD[4];
    #pragma unroll
    for (int nt = 0; nt < 8; nt++)
        #pragma unroll
        for (int i = 0; i < 4; i++) accK[nt][i] = 0.f;
    #pragma unroll
    for (int i = 0; i < 4; i++) accD[i] = 0.f;

    const uint32_t a_base = sb + (uint32_t)(w * 16 + ((lane >> 3) & 1) * 8 + (lane & 7)) * AROW
                          + (uint32_t)(lane >> 4) * 16;
    const uint32_t b_base = sb + KVOFF + (uint32_t)((lane >> 4) * 8 + (lane & 7)) * AROW
                          + (uint32_t)((lane >> 3) & 1) * 16;

    #pragma unroll
    for (int j = 0; j < 4; j++) {              // k-steps of 16
        const uint32_t ko = (uint32_t)j * 32;
        uint32_t a0, a1, a2, a3;
        ldsm_x4(a0, a1, a2, a3, a_base + ko);
        uint32_t bfr[8][2];
        #pragma unroll
        for (int p = 0; p < 4; p++)
            ldsm_x4(bfr[2*p][0], bfr[2*p][1], bfr[2*p+1][0], bfr[2*p+1][1],
                    b_base + (uint32_t)p * (16 * AROW) + ko);
        #pragma unroll
        for (int nt = 0; nt < 8; nt++)
            mma_f16(accK[nt], a0, a1, a2, a3, bfr[nt][0], bfr[nt][1]);
        // denominator: B[k,n] = K1[k] broadcast
        __half2 p0 = sK1[j * 8 + lc];
        __half2 p1 = sK1[j * 8 + 4 + lc];
        mma_f16(accD, a0, a1, a2, a3, *(uint32_t*)&p0, *(uint32_t*)&p1);
    }

    const int lr = lane >> 2;
    const float inv0 = 1.f / (accD[0] + EPSV);
    const float inv1 = 1.f / (accD[2] + EPSV);
    const int m = lt * 128 + w * 16 + lr;
    const size_t base0 = ((size_t)b * LSEQ + m) * DMODEL + h * DHEAD;
    #pragma unroll
    for (int nt = 0; nt < 8; nt++) {
        const int col = nt * 8 + lc * 2;
        __half2 h0 = __floats2half2_rn(accK[nt][0] * inv0, accK[nt][1] * inv0);
        __half2 h1 = __floats2half2_rn(accK[nt][2] * inv1, accK[nt][3] * inv1);
        *(uint32_t*)(g_ath + base0 + col)              = *(uint32_t*)&h0;
        *(uint32_t*)(g_ath + base0 + 8 * DMODEL + col) = *(uint32_t*)&h1;
    }
}

// ---------------- launch ------------------------------------------------------
extern "C" void kernel_launch(void* const* d_in, const int* in_sizes, int n_in,
                              void* d_out, int out_size)
{
    const float* x  = (const float*)d_in[0];
    const float* Wq = (const float*)d_in[1];
    const float* Wk = (const float*)d_in[2];
    const float* Wv = (const float*)d_in[3];
    const float* Wo = (const float*)d_in[4];
    float* out = (float*)d_out;

    __half *pXh, *pWth, *pAth;
    cudaGetSymbolAddress((void**)&pXh,  g_xh);
    cudaGetSymbolAddress((void**)&pWth, g_Wth);
    cudaGetSymbolAddress((void**)&pAth, g_ath);

    cudaFuncSetAttribute(gemm_f16_kernel<0>, cudaFuncAttributeMaxDynamicSharedMemorySize, GSMEM);
    cudaFuncSetAttribute(gemm_f16_kernel<1>, cudaFuncAttributeMaxDynamicSharedMemorySize, GSMEM);
    cudaFuncSetAttribute(kv_reduce_mma_kernel, cudaFuncAttributeMaxDynamicSharedMemorySize, KV_SMEM);

    const size_t WN = (size_t)DMODEL * DMODEL;

    to_half_kernel<<<MROWS * DMODEL / 4 / 256, 256>>>(x, pXh, MROWS * DMODEL / 4);
    transpose_all_kernel<<<dim3(DMODEL / 32, DMODEL / 32, 4), dim3(32, 8)>>>(Wq, Wk, Wv, Wo, pWth);

    // fused QKV GEMM
    gemm_f16_kernel<1><<<dim3(3 * DMODEL / BN, MROWS / BM), 256, GSMEM>>>(pXh, pWth, nullptr);

    kv_reduce_mma_kernel<<<dim3(KVCH, NHEADS, BATCH), 256, KV_SMEM>>>();
    kv_finalize_kernel<<<(BATCH*NHEADS*DHEAD*DHEAD + 255) / 256, 256>>>();

    attn_apply_mma_kernel<<<dim3(LSEQ / 128, NHEADS, BATCH), 256>>>();

    gemm_f16_kernel<0><<<dim3(DMODEL / BN, MROWS / BM), 256, GSMEM>>>(pAth, pWth + 3 * WN, out);
}

// round 16
// speedup vs baseline: 1.5141x; 1.5141x over previous
#include <cuda_runtime.h>
#include <cuda_fp16.h>
#include <math.h>
#include <stdint.h>

#define BATCH   4
#define LSEQ    8192
#define DMODEL  1024
#define NHEADS  16
#define DHEAD   64
#define MROWS   (BATCH * LSEQ)          // 32768
#define EPSV    1e-6f

// GEMM tiling: CTA 128x128, 8 warps (2x4), warp 64x32, k-stage 32 (fp16).
#define BM      128
#define BN      128
#define KSTG    32
#define NSTG    (DMODEL / KSTG)         // 32
#define RSB     80
#define BOFF    (BM * RSB)
#define STG_B   ((BM + BN) * RSB)       // 20480
#define GSMEM   (4 * STG_B)             // 81920

// kv_reduce (tensor-core) tiling
#define KVCH    16
#define KVL     (LSEQ / KVCH)           // 512
#define KROW    144
#define KBUF    (64 * KROW)             // 9216
#define KV_SMEM 66560
#define ONES16  0x3C003C00u

// ---------------- scratch (device globals; no allocations allowed) ----------
static __device__ __half g_xh  [(size_t)MROWS * DMODEL];
static __device__ __half g_Wth [(size_t)4 * DMODEL * DMODEL];           // [N,K] fp16 W
static __device__ __half g_Qfh [(size_t)MROWS * DMODEL];
static __device__ __half g_Kfh [(size_t)MROWS * DMODEL];
static __device__ __half g_Vh  [(size_t)MROWS * DMODEL];
static __device__ __half g_ath [(size_t)MROWS * DMODEL];
static __device__ float  g_KvP [(size_t)KVCH * BATCH * NHEADS * DHEAD * DHEAD];
static __device__ float  g_K1P [(size_t)KVCH * BATCH * NHEADS * DHEAD];
static __device__ __half g_Kvh [(size_t)BATCH * NHEADS * DHEAD * DHEAD];  // [bh][n][k] fp16
static __device__ __half g_K1h [(size_t)BATCH * NHEADS * DHEAD];

// ---------------- helpers ----------------------------------------------------
__device__ __forceinline__ uint32_t smem_u32(const void* p) {
    uint32_t a;
    asm("{ .reg .u64 t; cvta.to.shared.u64 t, %1; cvt.u32.u64 %0, t; }" : "=r"(a) : "l"(p));
    return a;
}
__device__ __forceinline__ void cp_async16(uint32_t saddr, const void* gptr) {
    asm volatile("cp.async.cg.shared.global [%0], [%1], 16;" :: "r"(saddr), "l"(gptr));
}
__device__ __forceinline__ void cp_commit() { asm volatile("cp.async.commit_group;"); }
template <int N> __device__ __forceinline__ void cp_wait() {
    asm volatile("cp.async.wait_group %0;" :: "n"(N));
}
__device__ __forceinline__ void mma_f16(float c[4],
                                        uint32_t a0, uint32_t a1, uint32_t a2, uint32_t a3,
                                        uint32_t b0, uint32_t b1)
{
    asm volatile("mma.sync.aligned.m16n8k16.row.col.f32.f16.f16.f32 "
                 "{%0,%1,%2,%3}, {%4,%5,%6,%7}, {%8,%9}, {%0,%1,%2,%3};"
                 : "+f"(c[0]), "+f"(c[1]), "+f"(c[2]), "+f"(c[3])
                 : "r"(a0), "r"(a1), "r"(a2), "r"(a3), "r"(b0), "r"(b1));
}
__device__ __forceinline__ void ldsm_x4(uint32_t& r0, uint32_t& r1, uint32_t& r2, uint32_t& r3,
                                        uint32_t addr)
{
    asm volatile("ldmatrix.sync.aligned.m8n8.x4.shared.b16 {%0,%1,%2,%3}, [%4];"
                 : "=r"(r0), "=r"(r1), "=r"(r2), "=r"(r3) : "r"(addr));
}
__device__ __forceinline__ void ldsm_x4t(uint32_t& r0, uint32_t& r1, uint32_t& r2, uint32_t& r3,
                                         uint32_t addr)
{
    asm volatile("ldmatrix.sync.aligned.m8n8.x4.trans.shared.b16 {%0,%1,%2,%3}, [%4];"
                 : "=r"(r0), "=r"(r1), "=r"(r2), "=r"(r3) : "r"(addr));
}

// ---------------- pre-passes --------------------------------------------------
__global__ void to_half_kernel(const float* __restrict__ in, __half* __restrict__ out, int n4)
{
    int i = blockIdx.x * blockDim.x + threadIdx.x;
    if (i < n4) {
        float4 v = ((const float4*)in)[i];
        __half2 h0 = __floats2half2_rn(v.x, v.y);
        __half2 h1 = __floats2half2_rn(v.z, v.w);
        ((uint2*)out)[i] = make_uint2(*(uint32_t*)&h0, *(uint32_t*)&h1);
    }
}

__global__ void transpose_all_kernel(const float* __restrict__ Wq, const float* __restrict__ Wk,
                                     const float* __restrict__ Wv, const float* __restrict__ Wo,
                                     __half* __restrict__ dst)
{
    __shared__ float t[32][33];
    const float* src = (blockIdx.z == 0) ? Wq : (blockIdx.z == 1) ? Wk
                     : (blockIdx.z == 2) ? Wv : Wo;
    __half* d = dst + (size_t)blockIdx.z * DMODEL * DMODEL;
    const int bx = blockIdx.x * 32, by = blockIdx.y * 32;
    const int tx = threadIdx.x, ty = threadIdx.y;
    #pragma unroll
    for (int j = ty; j < 32; j += 8)
        t[j][tx] = src[(size_t)(by + j) * DMODEL + bx + tx];
    __syncthreads();
    #pragma unroll
    for (int j = ty; j < 32; j += 8)
        d[(size_t)(bx + j) * DMODEL + by + tx] = __float2half_rn(t[tx][j]);
}

// ---------------- fp16 mma.sync GEMM with ldmatrix ---------------------------
template <int MODE>
__global__ __launch_bounds__(256, 2)
void gemm_f16_kernel(const __half* __restrict__ A, const __half* __restrict__ Bt,
                     float* __restrict__ Cf)
{
    extern __shared__ __align__(16) char smc[];
    const uint32_t sb = smem_u32(smc);

    const int tid  = threadIdx.x;
    const int lane = tid & 31;
    const int wid  = tid >> 5;
    const int bm   = blockIdx.y * BM;
    const int bn   = blockIdx.x * BN;
    const int wm   = (wid >> 2) * 64;
    const int wn   = (wid & 3) * 32;

    const int srow = tid >> 2;
    const int sch  = tid & 3;

    auto load_stage = [&](int s) {
        const uint32_t st = sb + (uint32_t)(s & 3) * STG_B;
        const int k0 = s * KSTG + sch * 8;
        cp_async16(st + (uint32_t)srow * RSB + sch * 16,
                   A + (size_t)(bm + srow) * DMODEL + k0);
        cp_async16(st + (uint32_t)(srow + 64) * RSB + sch * 16,
                   A + (size_t)(bm + srow + 64) * DMODEL + k0);
        cp_async16(st + BOFF + (uint32_t)srow * RSB + sch * 16,
                   Bt + (size_t)(bn + srow) * DMODEL + k0);
        cp_async16(st + BOFF + (uint32_t)(srow + 64) * RSB + sch * 16,
                   Bt + (size_t)(bn + srow + 64) * DMODEL + k0);
    };

    const uint32_t a_off = (uint32_t)(wm + ((lane >> 3) & 1) * 8 + (lane & 7)) * RSB
                         + (uint32_t)(lane >> 4) * 16;
    const uint32_t b_off = BOFF + (uint32_t)(wn + (lane >> 4) * 8 + (lane & 7)) * RSB
                         + (uint32_t)((lane >> 3) & 1) * 16;

    float acc[4][4][4];
    #pragma unroll
    for (int mt = 0; mt < 4; mt++)
        #pragma unroll
        for (int nt = 0; nt < 4; nt++)
            #pragma unroll
            for (int i = 0; i < 4; i++) acc[mt][nt][i] = 0.f;

    load_stage(0); cp_commit();
    load_stage(1); cp_commit();
    load_stage(2); cp_commit();

    #pragma unroll 1
    for (int c = 0; c < NSTG; c++) {
        cp_wait<2>();
        __syncthreads();

        if (c + 3 < NSTG) load_stage(c + 3);
        cp_commit();

        const uint32_t st = sb + (uint32_t)(c & 3) * STG_B;
        #pragma unroll
        for (int ks = 0; ks < 2; ks++) {
            const uint32_t ko = (uint32_t)ks * 32;
            uint32_t bfr[4][2];
            ldsm_x4(bfr[0][0], bfr[0][1], bfr[1][0], bfr[1][1], st + b_off + ko);
            ldsm_x4(bfr[2][0], bfr[2][1], bfr[3][0], bfr[3][1], st + b_off + 16 * RSB + ko);
            #pragma unroll
            for (int mt = 0; mt < 4; mt++) {
                uint32_t a0, a1, a2, a3;
                ldsm_x4(a0, a1, a2, a3, st + a_off + mt * (16 * RSB) + ko);
                #pragma unroll
                for (int nt = 0; nt < 4; nt++)
                    mma_f16(acc[mt][nt], a0, a1, a2, a3, bfr[nt][0], bfr[nt][1]);
            }
        }
    }

    const int lr = lane >> 2;
    const int lc = lane & 3;

    if (MODE == 0) {
        #pragma unroll
        for (int mt = 0; mt < 4; mt++)
            #pragma unroll
            for (int nt = 0; nt < 4; nt++) {
                const int row0 = bm + wm + mt * 16 + lr;
                const int col  = bn + wn + nt * 8 + lc * 2;
                *(float2*)(Cf + (size_t)row0 * DMODEL + col) =
                    make_float2(acc[mt][nt][0], acc[mt][nt][1]);
                *(float2*)(Cf + (size_t)(row0 + 8) * DMODEL + col) =
                    make_float2(acc[mt][nt][2], acc[mt][nt][3]);
            }
    } else {
        const int seg = bn >> 10;             // 0=Q, 1=K, 2=V
        const int bnl = bn & 1023;
        __half* outp = (seg == 0) ? g_Qfh : (seg == 1) ? g_Kfh : g_Vh;
        const bool phi = (seg < 2);
        #pragma unroll
        for (int mt = 0; mt < 4; mt++)
            #pragma unroll
            for (int nt = 0; nt < 4; nt++) {
                const int row0 = bm + wm + mt * 16 + lr;
                const int col  = bnl + wn + nt * 8 + lc * 2;
                float v[4];
                #pragma unroll
                for (int i = 0; i < 4; i++) {
                    float t = acc[mt][nt][i];
                    if (phi) t = (t > 0.f) ? (t + 1.f) : __expf(t);
                    v[i] = t;
                }
                __half2 h0 = __floats2half2_rn(v[0], v[1]);
                __half2 h1 = __floats2half2_rn(v[2], v[3]);
                *(uint32_t*)(outp + (size_t)row0 * DMODEL + col)       = *(uint32_t*)&h0;
                *(uint32_t*)(outp + (size_t)(row0 + 8) * DMODEL + col) = *(uint32_t*)&h1;
            }
    }
}

// ---------------- Kv / K1 reduction on tensor cores ---------------------------
__global__ __launch_bounds__(256, 2)
void kv_reduce_mma_kernel()
{
    extern __shared__ __align__(16) char km[];
    const uint32_t sb = smem_u32(km);
    const int tid  = threadIdx.x;
    const int lane = tid & 31;
    const int wid  = tid >> 5;
    const int chunk = blockIdx.x;
    const int h     = blockIdx.y;
    const int b     = blockIdx.z;
    const int bh    = b * NHEADS + h;
    const int mg = wid & 1;
    const int lg = wid >> 1;
    const int lb = lg * 16;

    auto load_sub = [&](int sub, int buf) {
        const uint32_t base = sb + (uint32_t)buf * (2 * KBUF);
        const int l0 = chunk * KVL + sub * 64;
        #pragma unroll
        for (int i = 0; i < 2; i++) {
            const int idx = tid + i * 256;
            const int row = idx >> 3, ch = idx & 7;
            size_t g = ((size_t)b * LSEQ + l0 + row) * DMODEL + h * DHEAD + ch * 8;
            cp_async16(base + (uint32_t)row * KROW + ch * 16,        g_Kfh + g);
            cp_async16(base + KBUF + (uint32_t)row * KROW + ch * 16, g_Vh + g);
        }
    };

    const uint32_t a_lane = (uint32_t)(lb + (lane >> 4) * 8 + (lane & 7)) * KROW
                          + (uint32_t)((lane >> 3) & 1) * 16;
    const uint32_t b_lane = KBUF + (uint32_t)(lb + ((lane >> 3) & 1) * 8 + (lane & 7)) * KROW
                          + (uint32_t)(lane >> 4) * 16;

    float accK[2][8][4];
    float accS[2][4];
    #pragma unroll
    for (int mt = 0; mt < 2; mt++) {
        #pragma unroll
        for (int nt = 0; nt < 8; nt++)
            #pragma unroll
            for (int i = 0; i < 4; i++) accK[mt][nt][i] = 0.f;
        #pragma unroll
        for (int i = 0; i < 4; i++) accS[mt][i] = 0.f;
    }

    load_sub(0, 0); cp_commit();

    #pragma unroll 1
    for (int sub = 0; sub < 8; sub++) {
        if (sub < 7) { load_sub(sub + 1, (sub + 1) & 1); cp_commit(); cp_wait<1>(); }
        else         { cp_wait<0>(); }
        __syncthreads();

        const uint32_t base = sb + (uint32_t)(sub & 1) * (2 * KBUF);
        uint32_t bfr[8][2];
        #pragma unroll
        for (int p = 0; p < 4; p++)
            ldsm_x4t(bfr[2*p][0], bfr[2*p][1], bfr[2*p+1][0], bfr[2*p+1][1],
                     base + b_lane + (uint32_t)p * 32);
        #pragma unroll
        for (int mt = 0; mt < 2; mt++) {
            uint32_t a0, a1, a2, a3;
            ldsm_x4t(a0, a1, a2, a3, base + a_lane + (uint32_t)(mg * 32 + mt * 16) * 2);
            #pragma unroll
            for (int nt = 0; nt < 8; nt++)
                mma_f16(accK[mt][nt], a0, a1, a2, a3, bfr[nt][0], bfr[nt][1]);
            mma_f16(accS[mt], a0, a1, a2, a3, ONES16, ONES16);
        }
        __syncthreads();
    }

    float* red   = (float*)km;             // [4][64][64]
    float* redk1 = (float*)(km + 65536);   // [4][64]
    const int lr = lane >> 2;
    const int lc = lane & 3;
    #pragma unroll
    for (int mt = 0; mt < 2; mt++) {
        const int m = mg * 32 + mt * 16 + lr;
        #pragma unroll
        for (int nt = 0; nt < 8; nt++) {
            const int n = nt * 8 + lc * 2;
            *(float2*)&red[((lg * 64 + m) * 64) + n]     = make_float2(accK[mt][nt][0], accK[mt][nt][1]);
            *(float2*)&red[((lg * 64 + m + 8) * 64) + n] = make_float2(accK[mt][nt][2], accK[mt][nt][3]);
        }
        if (lc == 0) {
            redk1[lg * 64 + m]     = accS[mt][0];
            redk1[lg * 64 + m + 8] = accS[mt][2];
        }
    }
    __syncthreads();

    for (int i = tid; i < 4096; i += 256) {
        float s = red[i] + red[4096 + i] + red[8192 + i] + red[12288 + i];
        g_KvP[((size_t)chunk * (BATCH * NHEADS) + bh) * 4096 + i] = s;
    }
    if (tid < 64) {
        float s = redk1[tid] + redk1[64 + tid] + redk1[128 + tid] + redk1[192 + tid];
        g_K1P[((size_t)chunk * (BATCH * NHEADS) + bh) * 64 + tid] = s;
    }
}

// ---------------- finalize: sum partials, emit fp16 Kv^T [n,k] and K1 --------
__global__ void kv_finalize_kernel()
{
    const int i = blockIdx.x * blockDim.x + threadIdx.x;
    const int KV_ELEMS = BATCH * NHEADS * DHEAD * DHEAD;
    const int K1_ELEMS = BATCH * NHEADS * DHEAD;
    if (i < KV_ELEMS) {
        float s = 0.f;
        #pragma unroll
        for (int c = 0; c < KVCH; c++) s += g_KvP[(size_t)c * KV_ELEMS + i];
        const int bh = i >> 12, rem = i & 4095, k = rem >> 6, n = rem & 63;
        g_Kvh[((size_t)bh << 12) + (n << 6) + k] = __float2half_rn(s);
    }
    if (i < K1_ELEMS) {
        float s = 0.f;
        #pragma unroll
        for (int c = 0; c < KVCH; c++) s += g_K1P[(size_t)c * K1_ELEMS + i];
        g_K1h[i] = __float2half_rn(s);
    }
}

// ---------------- apply (tensor cores): out = (Qf@Kv) / (Qf@K1 + eps) --------
#define AROW 144
__global__ __launch_bounds__(256, 3)
void attn_apply_mma_kernel()
{
    __shared__ __align__(16) char sm[128 * AROW + 64 * AROW + 128];
    const uint32_t sb = smem_u32(sm);
    const uint32_t KVOFF = 128 * AROW;
    const uint32_t K1OFF = KVOFF + 64 * AROW;

    const int tid  = threadIdx.x;
    const int lane = tid & 31;
    const int w    = tid >> 5;
    const int lt = blockIdx.x, h = blockIdx.y, b = blockIdx.z;
    const int bh = b * NHEADS + h;

    // Kv + K1 first (L2-hot after wave 1), then Qf stream
    for (int i = tid; i < 512; i += 256) {
        const int r = i >> 3, ch = i & 7;
        cp_async16(sb + KVOFF + (uint32_t)r * AROW + ch * 16,
                   g_Kvh + ((size_t)bh << 12) + r * 64 + ch * 8);
    }
    if (tid < 8)
        cp_async16(sb + K1OFF + tid * 16, g_K1h + bh * 64 + tid * 8);
    cp_commit();
    for (int i = tid; i < 1024; i += 256) {
        const int r = i >> 3, ch = i & 7;
        cp_async16(sb + (uint32_t)r * AROW + ch * 16,
                   g_Qfh + ((size_t)b * LSEQ + lt * 128 + r) * DMODEL + h * DHEAD + ch * 8);
    }
    cp_commit(); cp_wait<0>();
    __syncthreads();

    const __half2* sK1 = (const __half2*)(sm + K1OFF);
    const int lc = lane & 3;

    float accK[8][4];
    float accD[4];
    #pragma unroll
    for (int nt = 0; nt < 8; nt++)
        #pragma unroll
        for (int i = 0; i < 4; i++) accK[nt][i] = 0.f;
    #pragma unroll
    for (int i = 0; i < 4; i++) accD[i] = 0.f;

    const uint32_t a_base = sb + (uint32_t)(w * 16 + ((lane >> 3) & 1) * 8 + (lane & 7)) * AROW
                          + (uint32_t)(lane >> 4) * 16;
    const uint32_t b_base = sb + KVOFF + (uint32_t)((lane >> 4) * 8 + (lane & 7)) * AROW
                          + (uint32_t)((lane >> 3) & 1) * 16;

    #pragma unroll
    for (int j = 0; j < 4; j++) {              // k-steps of 16
        const uint32_t ko = (uint32_t)j * 32;
        uint32_t a0, a1, a2, a3;
        ldsm_x4(a0, a1, a2, a3, a_base + ko);
        uint32_t bfr[8][2];
        #pragma unroll
        for (int p = 0; p < 4; p++)
            ldsm_x4(bfr[2*p][0], bfr[2*p][1], bfr[2*p+1][0], bfr[2*p+1][1],
                    b_base + (uint32_t)p * (16 * AROW) + ko);
        #pragma unroll
        for (int nt = 0; nt < 8; nt++)
            mma_f16(accK[nt], a0, a1, a2, a3, bfr[nt][0], bfr[nt][1]);
        __half2 p0 = sK1[j * 8 + lc];
        __half2 p1 = sK1[j * 8 + 4 + lc];
        mma_f16(accD, a0, a1, a2, a3, *(uint32_t*)&p0, *(uint32_t*)&p1);
    }

    const int lr = lane >> 2;
    const float inv0 = 1.f / (accD[0] + EPSV);
    const float inv1 = 1.f / (accD[2] + EPSV);
    const int m = lt * 128 + w * 16 + lr;
    const size_t base0 = ((size_t)b * LSEQ + m) * DMODEL + h * DHEAD;
    #pragma unroll
    for (int nt = 0; nt < 8; nt++) {
        const int col = nt * 8 + lc * 2;
        __half2 h0 = __floats2half2_rn(accK[nt][0] * inv0, accK[nt][1] * inv0);
        __half2 h1 = __floats2half2_rn(accK[nt][2] * inv1, accK[nt][3] * inv1);
        *(uint32_t*)(g_ath + base0 + col)              = *(uint32_t*)&h0;
        *(uint32_t*)(g_ath + base0 + 8 * DMODEL + col) = *(uint32_t*)&h1;
    }
}

// ---------------- launch ------------------------------------------------------
extern "C" void kernel_launch(void* const* d_in, const int* in_sizes, int n_in,
                              void* d_out, int out_size)
{
    const float* x  = (const float*)d_in[0];
    const float* Wq = (const float*)d_in[1];
    const float* Wk = (const float*)d_in[2];
    const float* Wv = (const float*)d_in[3];
    const float* Wo = (const float*)d_in[4];
    float* out = (float*)d_out;

    __half *pXh, *pWth, *pAth;
    cudaGetSymbolAddress((void**)&pXh,  g_xh);
    cudaGetSymbolAddress((void**)&pWth, g_Wth);
    cudaGetSymbolAddress((void**)&pAth, g_ath);

    cudaFuncSetAttribute(gemm_f16_kernel<0>, cudaFuncAttributeMaxDynamicSharedMemorySize, GSMEM);
    cudaFuncSetAttribute(gemm_f16_kernel<1>, cudaFuncAttributeMaxDynamicSharedMemorySize, GSMEM);
    cudaFuncSetAttribute(kv_reduce_mma_kernel, cudaFuncAttributeMaxDynamicSharedMemorySize, KV_SMEM);

    const size_t WN = (size_t)DMODEL * DMODEL;

    to_half_kernel<<<MROWS * DMODEL / 4 / 256, 256>>>(x, pXh, MROWS * DMODEL / 4);
    transpose_all_kernel<<<dim3(DMODEL / 32, DMODEL / 32, 4), dim3(32, 8)>>>(Wq, Wk, Wv, Wo, pWth);

    // fused QKV GEMM
    gemm_f16_kernel<1><<<dim3(3 * DMODEL / BN, MROWS / BM), 256, GSMEM>>>(pXh, pWth, nullptr);

    kv_reduce_mma_kernel<<<dim3(KVCH, NHEADS, BATCH), 256, KV_SMEM>>>();
    kv_finalize_kernel<<<(BATCH*NHEADS*DHEAD*DHEAD + 255) / 256, 256>>>();

    attn_apply_mma_kernel<<<dim3(LSEQ / 128, NHEADS, BATCH), 256>>>();

    gemm_f16_kernel<0><<<dim3(DMODEL / BN, MROWS / BM), 256, GSMEM>>>(pAth, pWth + 3 * WN, out);
}